// round 10
// baseline (speedup 1.0000x reference)
#include <cuda_runtime.h>
#include <cstdint>

#define N_NODES 100000
#define N_EDGES 3200000
#define E4 (N_EDGES / 4)
#define N2 (N_NODES / 2)

#define GRID 296          // 2 CTAs/SM on 148 SMs — all co-resident (enforced below)
#define TPB  256
#define NTHREADS (GRID * TPB)

// Scratch (device globals — zero-initialized at module load; no allocation).
__device__ float  g_deg[N_NODES];    // consume-and-reset each replay
__device__ float  g_dinv[N_NODES];
__device__ float2 g_xs[N_NODES];
__device__ float2 g_agg1[N_NODES];
__device__ float2 g_ps[N_NODES];
__device__ float2 g_agg2[N_NODES];
__device__ unsigned g_bar;           // grid barrier counter; reset by k_reset node

__device__ __forceinline__ void red_add_f2(float2* addr, float2 v) {
    asm volatile("red.global.add.v2.f32 [%0], {%1, %2};"
                 :: "l"(addr), "f"(v.x), "f"(v.y) : "memory");
}
__device__ __forceinline__ void red_add_f(float* addr, float v) {
    asm volatile("red.global.add.f32 [%0], %1;"
                 :: "l"(addr), "f"(v) : "memory");
}

// Software grid barrier. All GRID CTAs are co-resident (launch_bounds-guaranteed),
// so spin-wait cannot deadlock. __threadfence (gpu scope) both publishes this
// thread's writes and invalidates L1D so post-barrier loads see fresh data.
__device__ __forceinline__ void gbar(int phase) {
    __threadfence();
    __syncthreads();
    if (threadIdx.x == 0) {
        asm volatile("red.global.add.u32 [%0], 1;" :: "l"(&g_bar) : "memory");
        const unsigned target = (unsigned)phase * GRID;
        while (*(volatile unsigned*)&g_bar < target) __nanosleep(64);
    }
    __syncthreads();
}

// ---------------------------------------------------------------------------
__global__ void __launch_bounds__(TPB, 2) k_fused(
    const float4* __restrict__ x4,
    const int4*   __restrict__ src4,
    const int4*   __restrict__ dst4,
    const float*  __restrict__ W1,   // [2,16]
    const float*  __restrict__ b1,   // [16]
    const float*  __restrict__ W2,   // [16,2]
    const float*  __restrict__ b2,   // [2]
    float4*       __restrict__ out4)
{
    const int tid = blockIdx.x * TPB + threadIdx.x;

    // ---- Phase 1: degree (4 edges / iter) ----
    for (int t = tid; t < E4; t += NTHREADS) {
        int4 d = dst4[t];
        red_add_f(&g_deg[d.x], 1.0f);
        red_add_f(&g_deg[d.y], 1.0f);
        red_add_f(&g_deg[d.z], 1.0f);
        red_add_f(&g_deg[d.w], 1.0f);
    }
    gbar(1);

    // ---- Phase 2: dinv + premultiplied features + self-loop seed (2 nodes) ----
    if (tid < N2) {
        int i = 2 * tid;
        float2 dg = *(const float2*)&g_deg[i];
        *(float2*)&g_deg[i] = make_float2(0.f, 0.f);   // reset for next replay
        float d0 = rsqrtf(dg.x + 1.0f);
        float d1 = rsqrtf(dg.y + 1.0f);
        *(float2*)&g_dinv[i] = make_float2(d0, d1);
        float4 xi = x4[tid];
        float4 xs = make_float4(xi.x * d0, xi.y * d0, xi.z * d1, xi.w * d1);
        *(float4*)&g_xs[i]   = xs;
        *(float4*)&g_agg1[i] = xs;
    }
    gbar(2);

    // ---- Phase 3: scatter layer 1 ----
    for (int t = tid; t < E4; t += NTHREADS) {
        int4 s = src4[t];
        int4 d = dst4[t];
        float2 v0 = __ldg(&g_xs[s.x]);
        float2 v1 = __ldg(&g_xs[s.y]);
        float2 v2 = __ldg(&g_xs[s.z]);
        float2 v3 = __ldg(&g_xs[s.w]);
        red_add_f2(&g_agg1[d.x], v0);
        red_add_f2(&g_agg1[d.y], v1);
        red_add_f2(&g_agg1[d.z], v2);
        red_add_f2(&g_agg1[d.w], v3);
    }
    gbar(3);

    // ---- Phase 4: MLP (norm -> W1 -> relu -> W2 -> premult), 2 nodes ----
    if (tid < N2) {
        int i = 2 * tid;
        float w1a[16], w1b[16], bb[16], w2x[16], w2y[16];
#pragma unroll
        for (int j = 0; j < 16; j++) {
            w1a[j] = __ldg(&W1[j]);
            w1b[j] = __ldg(&W1[16 + j]);
            bb[j]  = __ldg(&b1[j]);
            w2x[j] = __ldg(&W2[2 * j]);
            w2y[j] = __ldg(&W2[2 * j + 1]);
        }
        float2 dv = *(const float2*)&g_dinv[i];
        float4 tt = *(const float4*)&g_agg1[i];
        float a0x = tt.x * dv.x, a0y = tt.y * dv.x;
        float a1x = tt.z * dv.y, a1y = tt.w * dv.y;
        float p0x = 0.f, p0y = 0.f, p1x = 0.f, p1y = 0.f;
#pragma unroll
        for (int j = 0; j < 16; j++) {
            float h0 = fmaxf(a0x * w1a[j] + a0y * w1b[j] + bb[j], 0.f);
            float h1 = fmaxf(a1x * w1a[j] + a1y * w1b[j] + bb[j], 0.f);
            p0x += h0 * w2x[j];  p0y += h0 * w2y[j];
            p1x += h1 * w2x[j];  p1y += h1 * w2y[j];
        }
        float4 ps = make_float4(p0x * dv.x, p0y * dv.x, p1x * dv.y, p1y * dv.y);
        *(float4*)&g_ps[i]   = ps;
        *(float4*)&g_agg2[i] = ps;
    }
    gbar(4);

    // ---- Phase 5: scatter layer 2 ----
    for (int t = tid; t < E4; t += NTHREADS) {
        int4 s = src4[t];
        int4 d = dst4[t];
        float2 v0 = __ldg(&g_ps[s.x]);
        float2 v1 = __ldg(&g_ps[s.y]);
        float2 v2 = __ldg(&g_ps[s.z]);
        float2 v3 = __ldg(&g_ps[s.w]);
        red_add_f2(&g_agg2[d.x], v0);
        red_add_f2(&g_agg2[d.y], v1);
        red_add_f2(&g_agg2[d.z], v2);
        red_add_f2(&g_agg2[d.w], v3);
    }
    gbar(5);

    // ---- Phase 6: bias + log_softmax, 2 nodes ----
    if (tid < N2) {
        int i = 2 * tid;
        float bx = __ldg(&b2[0]), by = __ldg(&b2[1]);
        float2 dv = *(const float2*)&g_dinv[i];
        float4 tt = *(const float4*)&g_agg2[i];
        float z0x = tt.x * dv.x + bx, z0y = tt.y * dv.x + by;
        float z1x = tt.z * dv.y + bx, z1y = tt.w * dv.y + by;
        float m0 = fmaxf(z0x, z0y);
        float l0 = m0 + __logf(__expf(z0x - m0) + __expf(z0y - m0));
        float m1 = fmaxf(z1x, z1y);
        float l1 = m1 + __logf(__expf(z1x - m1) + __expf(z1y - m1));
        out4[tid] = make_float4(z0x - l0, z0y - l0, z1x - l1, z1y - l1);
    }
}

// Runs after k_fused (kernel boundary = all CTAs done): reset barrier counter
// so the next graph replay starts from 0.
__global__ void k_reset() { g_bar = 0; }

// ---------------------------------------------------------------------------
extern "C" void kernel_launch(void* const* d_in, const int* in_sizes, int n_in,
                              void* d_out, int out_size) {
    const float* x  = (const float*)d_in[0];   // [N,2]
    const int*   ei = (const int*)d_in[1];     // [2,E] int32
    const float* W1 = (const float*)d_in[2];
    const float* b1 = (const float*)d_in[3];
    const float* W2 = (const float*)d_in[4];
    const float* b2 = (const float*)d_in[5];

    const int4* src4 = (const int4*)ei;
    const int4* dst4 = (const int4*)(ei + N_EDGES);
    const float4* x4 = (const float4*)x;
    float4* out4 = (float4*)d_out;

    k_fused<<<GRID, TPB>>>(x4, src4, dst4, W1, b1, W2, b2, out4);
    k_reset<<<1, 1>>>();
}